// round 16
// baseline (speedup 1.0000x reference)
#include <cuda_runtime.h>
#include <cuda_fp16.h>
#include <cstdint>

// Problem constants (fixed shapes for this problem instance)
#define NN   50000
#define EE   800000
#define LM   1024
#define HH   128
#define OUTC 64

// ---------------- scratch (static __device__, no allocation) ----------------
__device__ __half g_wth [(size_t)LM * LM];  // Wl^T fp16  [1024,1024]
__device__ __half g_w1th[(size_t)HH * LM];  // W1^T fp16  [128,1024]
__device__ __half g_w3t [(size_t)OUTC * HH];// W3^T fp16  [64,128]
__device__ float  g_hp1f[(size_t)NN * HH];  // h1 @ W1 (fp32, atomic split-K)
__device__ __half g_hp1h[(size_t)NN * HH];  // hp1 fp16 (for gather)
__device__ __half g_h2h [(size_t)NN * HH];  // conv1 output relu'd (fp16)
__device__ float  g_hp3[(size_t)NN * OUTC]; // h2 @ W3 (fp32)
__device__ float g_deg [NN];
__device__ float g_dis [NN];
__device__ int   g_cnt [NN];
__device__ int   g_rowptr[NN + 1];
__device__ int   g_bsum[64];
__device__ int   g_csr_src [EE];
__device__ float g_csr_coef[EE];
__device__ int   g_is64;

// ---------------- portable PTX helpers (sm_80+, compile for compute_103) ----
__device__ __forceinline__ uint32_t smem_to_u32(const void* p) {
    uint32_t a;
    asm("{ .reg .u64 t; cvta.to.shared.u64 t, %1; cvt.u32.u64 %0, t; }" : "=r"(a) : "l"(p));
    return a;
}
#define CP_ASYNC16(saddr, gaddr, sz) \
    asm volatile("cp.async.cg.shared.global [%0], [%1], 16, %2;" \
        :: "r"(saddr), "l"(gaddr), "r"(sz))
#define CP_COMMIT() asm volatile("cp.async.commit_group;" ::: "memory")
#define CP_WAIT(n)  asm volatile("cp.async.wait_group %0;" :: "n"(n) : "memory")
#define LDSM_X4(R, ADDR) \
    asm volatile("ldmatrix.sync.aligned.m8n8.x4.shared.b16 {%0,%1,%2,%3}, [%4];" \
        : "=r"((R)[0]), "=r"((R)[1]), "=r"((R)[2]), "=r"((R)[3]) : "r"(ADDR))

__device__ __forceinline__ void mma_fp16(float* d, const uint32_t* a,
                                         uint32_t b0, uint32_t b1) {
    asm volatile(
        "mma.sync.aligned.m16n8k16.row.col.f32.f16.f16.f32 "
        "{%0,%1,%2,%3}, {%4,%5,%6,%7}, {%8,%9}, {%0,%1,%2,%3};"
        : "+f"(d[0]), "+f"(d[1]), "+f"(d[2]), "+f"(d[3])
        : "r"(a[0]), "r"(a[1]), "r"(a[2]), "r"(a[3]), "r"(b0), "r"(b1));
}

// ---------------- buffer selectors ----------------
__device__ __forceinline__ const __half* sel_a(int SEL) {
    return g_h2h;                      // only GEMM3 uses the fp16 A path now
}
__device__ __forceinline__ const __half* sel_b(int SEL) {
    if (SEL == 1) return g_wth;
    return g_w3t;
}

// edge index fetch honoring detected dtype
__device__ __forceinline__ int edge_at(const void* ei, long long idx) {
    if (g_is64) return (int)((const long long*)ei)[idx];
    return ((const int*)ei)[idx];
}

// ---------------- fused dtype detection + init ----------------
__global__ void k_prep(const unsigned int* __restrict__ w, int n) {
    int i = blockIdx.x * blockDim.x + threadIdx.x;
    if (i == 0) {
        int is64 = 1;
        for (int j = 1; j < 64; j += 2)
            if (w[j] != 0u) { is64 = 0; break; }
        g_is64 = is64;
    }
    if (i < n) { g_deg[i] = 1.0f; g_cnt[i] = 0; }
}

__global__ void k_count(const void* __restrict__ ei, const float* __restrict__ ew, int e_) {
    int e = blockIdx.x * blockDim.x + threadIdx.x;
    if (e >= e_) return;
    int d = edge_at(ei, (long long)e_ + e);
    atomicAdd(&g_deg[d], ew[e]);
    atomicAdd(&g_cnt[d], 1);
}

// multi-block scan, phase A
__global__ void k_scanA(int n) {
    __shared__ int wsum[32];
    int tid  = threadIdx.x;
    int warp = tid >> 5;
    int idx  = blockIdx.x * 1024 + tid;
    int v = (idx < n) ? g_cnt[idx] : 0;
    int inc = v;
    #pragma unroll
    for (int o = 1; o < 32; o <<= 1) {
        int nb = __shfl_up_sync(0xffffffffu, inc, o);
        if ((tid & 31) >= o) inc += nb;
    }
    if ((tid & 31) == 31) wsum[warp] = inc;
    __syncthreads();
    if (tid < 32) {
        int w = wsum[tid];
        #pragma unroll
        for (int o = 1; o < 32; o <<= 1) {
            int nb = __shfl_up_sync(0xffffffffu, w, o);
            if (tid >= o) w += nb;
        }
        wsum[tid] = w;
    }
    __syncthreads();
    int excl = inc - v + ((warp > 0) ? wsum[warp - 1] : 0);
    if (idx < n) {
        g_rowptr[idx] = excl;
        g_cnt[idx]    = 0;
        g_dis[idx]    = rsqrtf(g_deg[idx]);
    }
    if (tid == 0) g_bsum[blockIdx.x] = wsum[31];
}

// phase B: add block offsets
__global__ void k_scanB(int n, int e_) {
    __shared__ int s_off;
    int tid = threadIdx.x;
    if (tid < 32) {
        int acc = 0;
        for (int i = tid; i < (int)blockIdx.x; i += 32) acc += g_bsum[i];
        #pragma unroll
        for (int o = 16; o > 0; o >>= 1)
            acc += __shfl_down_sync(0xffffffffu, acc, o);
        if (tid == 0) s_off = acc;
    }
    __syncthreads();
    int idx = blockIdx.x * 1024 + tid;
    if (idx < n) g_rowptr[idx] += s_off;
    if (idx == n - 1) g_rowptr[n] = e_;
}

__global__ void k_fill(const void* __restrict__ ei, const float* __restrict__ ew, int e_) {
    int e = blockIdx.x * blockDim.x + threadIdx.x;
    if (e >= e_) return;
    int s = edge_at(ei, e);
    int d = edge_at(ei, (long long)e_ + e);
    int p = g_rowptr[d] + atomicAdd(&g_cnt[d], 1);
    g_csr_src[p]  = s;
    g_csr_coef[p] = g_dis[s] * ew[e] * g_dis[d];
}

// ---------------- fused weight transpose+convert + hp1 zero ----------------
__global__ void k_cvt_w(const float* __restrict__ Wl, const float* __restrict__ W1,
                        const float* __restrict__ W3) {
    int idx = blockIdx.x * blockDim.x + threadIdx.x;
    if (idx < LM * LM) {
        int k = idx / LM, nn = idx % LM;
        g_wth[(size_t)nn * LM + k] = __float2half(Wl[idx]);
        return;
    }
    idx -= LM * LM;
    if (idx < LM * HH) {
        int k = idx / HH, nn = idx % HH;
        g_w1th[(size_t)nn * LM + k] = __float2half(W1[idx]);
        return;
    }
    idx -= LM * HH;
    if (idx < HH * OUTC) {
        int k = idx / OUTC, nn = idx % OUTC;
        g_w3t[(size_t)nn * HH + k] = __float2half(W3[idx]);
        return;
    }
    idx -= HH * OUTC;
    if (idx < NN * HH) g_hp1f[idx] = 0.0f;
}

// ---------------- hp1 fp32 -> fp16 ----------------
__global__ void k_cvt_hp1(long long total2) {
    long long i = (long long)blockIdx.x * blockDim.x + threadIdx.x;
    if (i >= total2) return;
    float2 v = ((const float2*)g_hp1f)[i];
    ((__half2*)g_hp1h)[i] = __floats2half2_rn(v.x, v.y);
}

// ---------------- mma.sync fp16 GEMM ----------------
// FUSED=1 (GEMM1): A = xout fp32 (LDG->cvt->STS, 2-stage); B = Wl^T (3-stage
//   cp.async). Epilogue: h1 tile = relu(acc + bl + c*Wc + x*Wa) -> fp16 smem,
//   then 4 extra MMA iterations against W1 slice -> atomicAdd into g_hp1f.
//   h1 is never materialized in gmem.
// FUSED=0 (GEMM3): fp16 A+B via 3-stage cp.async, fp32 store to g_hp3.
template <int FUSED, int BSEL, int KDIM, int BN, int THREADS>
__global__ __launch_bounds__(THREADS, 2)
void k_gemm_mma(int M, const float* __restrict__ Af32,
                const float* __restrict__ cvec, const float* __restrict__ xvec,
                const float* __restrict__ Wc,   const float* __restrict__ Wa,
                const float* __restrict__ bl) {
    constexpr int BK  = 32;
    constexpr int NIT = KDIM / BK;
    constexpr int ASZ = 8192;               // 128 rows x 32 fp16
    constexpr int BSZ = BN * BK * 2;
    constexpr int NSTAGE = 3;

    extern __shared__ char smem[];
    const uint32_t sbase0 = smem_to_u32(smem);
    // FUSED layout: [A0 8K][A1 8K][B0 8K][B1 8K][B2 8K] then (epilogue reuse)
    //               [h1 tile 32K @0][W1 slice 32K @32768]
    // FUSED==0:     [(A+B) stage0][stage1][stage2]
    const uint32_t bbase = FUSED ? (sbase0 + 2 * ASZ) : sbase0;
    constexpr int BSTRIDE = FUSED ? BSZ : (ASZ + BSZ);
    constexpr uint32_t BOFF = FUSED ? 0 : ASZ;

    const int tid    = threadIdx.x;
    const int lane   = tid & 31;
    const int wid    = tid >> 5;
    const int warp_m = wid & 3;
    const int warp_n = wid >> 2;

    const int block_row = blockIdx.y * 128;
    const int block_col = blockIdx.x * BN;

    const __half* __restrict__ Ah = sel_a(0);
    const __half* __restrict__ Bh = sel_b(BSEL);

    // FUSED fixed-slot mapping (valid only for THREADS==256)
    const int r0  = tid >> 2,          cb0 = tid & 3;
    const int r1  = (tid + 256) >> 2,  cb1 = tid & 3;
    const uint32_t so0 = (uint32_t)(r0 * 64 + ((cb0 ^ ((r0 >> 1) & 3)) * 16));
    const uint32_t so1 = (uint32_t)(r1 * 64 + ((cb1 ^ ((r1 >> 1) & 3)) * 16));

    auto issue_B = [&](int stage, int k0) {
        uint32_t sb = bbase + stage * BSTRIDE + BOFF;
        #pragma unroll
        for (int i = tid; i < BN * 4; i += THREADS) {
            int r = i >> 2, cb = i & 3;
            uint32_t so = (uint32_t)(r * 64 + ((cb ^ ((r >> 1) & 3)) * 16));
            size_t gb = (size_t)(block_col + r) * KDIM + k0 + cb * 8;
            CP_ASYNC16(sb + so, (const char*)(Bh + gb), 16u);
        }
        CP_COMMIT();
    };
    // strided loop: correct for any THREADS
    auto issue_A_async = [&](int stage, int k0) {   // FUSED==0 path
        uint32_t sb = bbase + stage * BSTRIDE;
        #pragma unroll
        for (int i = tid; i < 512; i += THREADS) {
            int r = i >> 2, cb = i & 3;
            uint32_t so = (uint32_t)(r * 64 + ((cb ^ ((r >> 1) & 3)) * 16));
            long long arow = block_row + r;
            size_t ga = (size_t)arow * KDIM + k0 + cb * 8;
            uint32_t asz = (arow < M) ? 16u : 0u;
            CP_ASYNC16(sb + so, (const char*)(Ah + ga), asz);
        }
    };

    // fp32 A register staging (FUSED==1, THREADS==256)
    float4 arg[4];
    auto ldg_A = [&](int k0) {
        long long arow0 = block_row + r0;
        long long arow1 = block_row + r1;
        if (arow0 < M) {
            const float* p = Af32 + (size_t)arow0 * KDIM + k0 + cb0 * 8;
            arg[0] = *(const float4*)p;
            arg[1] = *(const float4*)(p + 4);
        } else {
            arg[0] = arg[1] = make_float4(0.f, 0.f, 0.f, 0.f);
        }
        if (arow1 < M) {
            const float* p = Af32 + (size_t)arow1 * KDIM + k0 + cb1 * 8;
            arg[2] = *(const float4*)p;
            arg[3] = *(const float4*)(p + 4);
        } else {
            arg[2] = arg[3] = make_float4(0.f, 0.f, 0.f, 0.f);
        }
    };
    auto sts_A = [&](int buf) {
        uint32_t off = buf * ASZ;
        uint4 v;
        __half2 h;
        h = __floats2half2_rn(arg[0].x, arg[0].y); v.x = *(uint32_t*)&h;
        h = __floats2half2_rn(arg[0].z, arg[0].w); v.y = *(uint32_t*)&h;
        h = __floats2half2_rn(arg[1].x, arg[1].y); v.z = *(uint32_t*)&h;
        h = __floats2half2_rn(arg[1].z, arg[1].w); v.w = *(uint32_t*)&h;
        *(uint4*)(smem + off + so0) = v;
        h = __floats2half2_rn(arg[2].x, arg[2].y); v.x = *(uint32_t*)&h;
        h = __floats2half2_rn(arg[2].z, arg[2].w); v.y = *(uint32_t*)&h;
        h = __floats2half2_rn(arg[3].x, arg[3].y); v.z = *(uint32_t*)&h;
        h = __floats2half2_rn(arg[3].z, arg[3].w); v.w = *(uint32_t*)&h;
        *(uint4*)(smem + off + so1) = v;
    };

    float acc[2][8][4];
    #pragma unroll
    for (int i = 0; i < 2; i++)
        #pragma unroll
        for (int j = 0; j < 8; j++)
            #pragma unroll
            for (int q = 0; q < 4; q++) acc[i][j][q] = 0.0f;

    // ---- prologue ----
    if (FUSED) {
        ldg_A(0);
        issue_B(0, 0);
        issue_B(1, BK);
        sts_A(0);
        CP_WAIT(1);
        __syncthreads();
    } else {
        issue_A_async(0, 0); issue_B(0, 0);
        issue_A_async(1, BK); issue_B(1, BK);
    }

    int stage = 0;
    for (int it = 0; it < NIT; it++) {
        if (FUSED) {
            if (it + 1 < NIT) ldg_A((it + 1) * BK);
            if (it + 2 < NIT) issue_B((it + 2) % NSTAGE, (it + 2) * BK);
        } else {
            if (it + 2 < NIT) {
                issue_A_async((it + 2) % NSTAGE, (it + 2) * BK);
                issue_B((it + 2) % NSTAGE, (it + 2) * BK);
                CP_WAIT(2);
            } else {
                CP_WAIT(0);
            }
            __syncthreads();
        }

        const uint32_t abuf = FUSED ? (sbase0 + (it & 1) * ASZ)
                                    : (bbase + stage * BSTRIDE);
        const uint32_t bbuf = bbase + stage * BSTRIDE + BOFF;
        #pragma unroll
        for (int ks = 0; ks < 2; ks++) {
            uint32_t aH[2][4];
            #pragma unroll
            for (int mt = 0; mt < 2; mt++) {
                int row = warp_m * 32 + mt * 16 + (lane & 15);
                int cb  = ks * 2 + (lane >> 4);
                uint32_t off = (uint32_t)(row * 64 + ((cb ^ ((row >> 1) & 3)) * 16));
                LDSM_X4(aH[mt], abuf + off);
            }
            #pragma unroll
            for (int g = 0; g < 4; g++) {
                uint32_t bh[4];
                int row = warp_n * 64 + g * 16 + (lane & 15);
                int cb  = ks * 2 + (lane >> 4);
                uint32_t off = (uint32_t)(row * 64 + ((cb ^ ((row >> 1) & 3)) * 16));
                LDSM_X4(bh, bbuf + off);
                #pragma unroll
                for (int mt = 0; mt < 2; mt++) {
                    #pragma unroll
                    for (int sub = 0; sub < 2; sub++) {
                        int nt = g * 2 + sub;
                        mma_fp16(acc[mt][nt], aH[mt], bh[sub], bh[sub + 2]);
                    }
                }
            }
        }
        __syncthreads();
        if (FUSED) {
            if (it + 1 < NIT) sts_A((it + 1) & 1);
            if (it + 2 < NIT) { CP_WAIT(1); }
            else if (it + 1 < NIT) { CP_WAIT(0); }
            __syncthreads();
        }
        stage = (stage + 1 == NSTAGE) ? 0 : stage + 1;
    }

    if (FUSED) {
        // ===== fused GEMM1 epilogue + GEMM2 split-K =====
        // (1) kick W1 slice loads: [128 outs x 128 K] as 4 BK32 chunks @ +32768
        #pragma unroll
        for (int i = tid; i < 2048; i += THREADS) {
            int kt = i >> 9;
            int r  = (i >> 2) & 127;         // out col (0..127)
            int cb = i & 3;
            uint32_t so = (uint32_t)(32768 + kt * 8192 + r * 64 +
                                     ((cb ^ ((r >> 1) & 3)) * 16));
            size_t g = (size_t)r * LM + (size_t)blockIdx.x * 128 + kt * 32 + cb * 8;
            CP_ASYNC16(sbase0 + so, (const char*)(g_w1th + g), 16u);
        }
        CP_COMMIT();

        // (2) epilogue math -> h1 tile (fp16, swizzled BK32 chunks) in smem @ +0
        float cvr[4], xvr[4];
        #pragma unroll
        for (int mt = 0; mt < 2; mt++)
            #pragma unroll
            for (int h = 0; h < 2; h++) {
                int rl = warp_m * 32 + mt * 16 + (lane >> 2) + h * 8;
                long long row = block_row + rl;
                int idx = mt * 2 + h;
                if (row < M) { cvr[idx] = cvec[row]; xvr[idx] = xvec[row]; }
                else         { cvr[idx] = 0.f;       xvr[idx] = 0.f; }
            }
        #pragma unroll
        for (int nt = 0; nt < 8; nt++) {
            int col  = warp_n * 64 + nt * 8 + (lane & 3) * 2;   // local 0..127
            int gcol = block_col + col;                          // global 0..1023
            float bl0 = bl[gcol],  bl1 = bl[gcol + 1];
            float wc0 = Wc[gcol],  wc1 = Wc[gcol + 1];
            float wa0 = Wa[gcol],  wa1 = Wa[gcol + 1];
            int kt = col >> 5, kc = col & 31;
            #pragma unroll
            for (int mt = 0; mt < 2; mt++)
                #pragma unroll
                for (int h = 0; h < 2; h++) {
                    int rl = warp_m * 32 + mt * 16 + (lane >> 2) + h * 8;
                    int idx = mt * 2 + h;
                    float v0 = fmaxf(acc[mt][nt][h * 2 + 0] + bl0 +
                                     cvr[idx] * wc0 + xvr[idx] * wa0, 0.f);
                    float v1 = fmaxf(acc[mt][nt][h * 2 + 1] + bl1 +
                                     cvr[idx] * wc1 + xvr[idx] * wa1, 0.f);
                    uint32_t a = (uint32_t)(kt * 8192 + rl * 64 +
                        (((kc >> 3) ^ ((rl >> 1) & 3)) * 16) + (kc & 7) * 2);
                    *(__half2*)(smem + a) = __floats2half2_rn(v0, v1);
                }
        }
        __syncthreads();
        CP_WAIT(0);
        __syncthreads();

        // (3) fused MMA: hp1_partial = h1_tile @ W1_slice  (K=128, 4 BK32 iters)
        float acc2[2][8][4];
        #pragma unroll
        for (int i = 0; i < 2; i++)
            #pragma unroll
            for (int j = 0; j < 8; j++)
                #pragma unroll
                for (int q = 0; q < 4; q++) acc2[i][j][q] = 0.0f;

        #pragma unroll
        for (int kt = 0; kt < 4; kt++) {
            const uint32_t abuf = sbase0 + kt * 8192;
            const uint32_t bbuf = sbase0 + 32768 + kt * 8192;
            #pragma unroll
            for (int ks = 0; ks < 2; ks++) {
                uint32_t aH[2][4];
                #pragma unroll
                for (int mt = 0; mt < 2; mt++) {
                    int row = warp_m * 32 + mt * 16 + (lane & 15);
                    int cb  = ks * 2 + (lane >> 4);
                    uint32_t off = (uint32_t)(row * 64 + ((cb ^ ((row >> 1) & 3)) * 16));
                    LDSM_X4(aH[mt], abuf + off);
                }
                #pragma unroll
                for (int g = 0; g < 4; g++) {
                    uint32_t bh[4];
                    int row = warp_n * 64 + g * 16 + (lane & 15);
                    int cb  = ks * 2 + (lane >> 4);
                    uint32_t off = (uint32_t)(row * 64 + ((cb ^ ((row >> 1) & 3)) * 16));
                    LDSM_X4(bh, bbuf + off);
                    #pragma unroll
                    for (int mt = 0; mt < 2; mt++) {
                        #pragma unroll
                        for (int sub = 0; sub < 2; sub++) {
                            int nt = g * 2 + sub;
                            mma_fp16(acc2[mt][nt], aH[mt], bh[sub], bh[sub + 2]);
                        }
                    }
                }
            }
        }

        // (4) split-K reduce into g_hp1f
        #pragma unroll
        for (int nt = 0; nt < 8; nt++) {
            int o = warp_n * 64 + nt * 8 + (lane & 3) * 2;     // out col 0..127
            #pragma unroll
            for (int mt = 0; mt < 2; mt++)
                #pragma unroll
                for (int h = 0; h < 2; h++) {
                    int rl = warp_m * 32 + mt * 16 + (lane >> 2) + h * 8;
                    long long row = block_row + rl;
                    if (row < M) {
                        atomicAdd(&g_hp1f[row * HH + o],     acc2[mt][nt][h * 2 + 0]);
                        atomicAdd(&g_hp1f[row * HH + o + 1], acc2[mt][nt][h * 2 + 1]);
                    }
                }
        }
    } else {
        // ===== GEMM3 epilogue: fp32 store =====
        #pragma unroll
        for (int nt = 0; nt < 8; nt++) {
            int col = block_col + warp_n * 64 + nt * 8 + (lane & 3) * 2;
            #pragma unroll
            for (int mt = 0; mt < 2; mt++) {
                int rbase = block_row + warp_m * 32 + mt * 16 + (lane >> 2);
                #pragma unroll
                for (int h = 0; h < 2; h++) {
                    int row = rbase + h * 8;
                    if (row >= M) continue;
                    float2 f2;
                    f2.x = acc[mt][nt][h * 2 + 0];
                    f2.y = acc[mt][nt][h * 2 + 1];
                    *(float2*)&g_hp3[(size_t)row * OUTC + col] = f2;
                }
            }
        }
    }
}

// ---------------- conv1 aggregation (fp16 in/out, CSR gather, warp/node) ----
__global__ void k_agg_h(const float* __restrict__ bias, int n) {
    int warp = (blockIdx.x * blockDim.x + threadIdx.x) >> 5;
    int lane = threadIdx.x & 31;
    if (warp >= n) return;
    const int node = warp;
    float acc[4];

    float selfc = g_dis[node] * g_dis[node];
    {
        uint2 v = *(const uint2*)&g_hp1h[(size_t)node * HH + lane * 4];
        float2 fa = __half22float2(*reinterpret_cast<__half2*>(&v.x));
        float2 fb = __half22float2(*reinterpret_cast<__half2*>(&v.y));
        acc[0] = selfc * fa.x; acc[1] = selfc * fa.y;
        acc[2] = selfc * fb.x; acc[3] = selfc * fb.y;
    }
    int beg = g_rowptr[node];
    int end = g_rowptr[node + 1];
    for (int e = beg; e < end; e++) {
        int   s  = g_csr_src[e];
        float cf = g_csr_coef[e];
        uint2 v = *(const uint2*)&g_hp1h[(size_t)s * HH + lane * 4];
        float2 fa = __half22float2(*reinterpret_cast<__half2*>(&v.x));
        float2 fb = __half22float2(*reinterpret_cast<__half2*>(&v.y));
        acc[0] = fmaf(cf, fa.x, acc[0]);
        acc[1] = fmaf(cf, fa.y, acc[1]);
        acc[2] = fmaf(cf, fb.x, acc[2]);
        acc[3] = fmaf(cf, fb.y, acc[3]);
    }
    float b0 = bias[lane * 4 + 0], b1 = bias[lane * 4 + 1];
    float b2 = bias[lane * 4 + 2], b3 = bias[lane * 4 + 3];
    __half2 o0, o1;
    o0.x = __float2half(fmaxf(acc[0] + b0, 0.f));
    o0.y = __float2half(fmaxf(acc[1] + b1, 0.f));
    o1.x = __float2half(fmaxf(acc[2] + b2, 0.f));
    o1.y = __float2half(fmaxf(acc[3] + b3, 0.f));
    uint2 ov;
    ov.x = *reinterpret_cast<uint32_t*>(&o0);
    ov.y = *reinterpret_cast<uint32_t*>(&o1);
    *(uint2*)&g_h2h[(size_t)node * HH + lane * 4] = ov;
}

// ---------------- conv3 aggregation (fp32, writes final out) ----------------
__global__ void k_agg_f(const float* __restrict__ bias, float* __restrict__ out, int n) {
    int warp = (blockIdx.x * blockDim.x + threadIdx.x) >> 5;
    int lane = threadIdx.x & 31;
    if (warp >= n) return;
    const int node = warp;
    float acc[2];

    float selfc = g_dis[node] * g_dis[node];
    {
        float2 v = *(const float2*)&g_hp3[(size_t)node * OUTC + lane * 2];
        acc[0] = selfc * v.x; acc[1] = selfc * v.y;
    }
    int beg = g_rowptr[node];
    int end = g_rowptr[node + 1];
    for (int e = beg; e < end; e++) {
        int   s  = g_csr_src[e];
        float cf = g_csr_coef[e];
        float2 v = *(const float2*)&g_hp3[(size_t)s * OUTC + lane * 2];
        acc[0] = fmaf(cf, v.x, acc[0]);
        acc[1] = fmaf(cf, v.y, acc[1]);
    }
    float2 o;
    o.x = acc[0] + bias[lane * 2 + 0];
    o.y = acc[1] + bias[lane * 2 + 1];
    *(float2*)&out[(size_t)node * OUTC + lane * 2] = o;
}

// ---------------- launch ----------------
extern "C" void kernel_launch(void* const* d_in, const int* in_sizes, int n_in,
                              void* d_out, int out_size) {
    const float* x    = (const float*)d_in[0];
    const float* xout = (const float*)d_in[1];
    const float* c    = (const float*)d_in[2];
    const void*  ei   = d_in[3];
    const float* ew   = (const float*)d_in[4];
    const float* Wa   = (const float*)d_in[5];
    const float* Wc   = (const float*)d_in[6];
    const float* Wl   = (const float*)d_in[7];
    const float* bl   = (const float*)d_in[8];
    const float* W1   = (const float*)d_in[9];
    const float* b1   = (const float*)d_in[10];
    const float* W3   = (const float*)d_in[11];
    const float* b3   = (const float*)d_in[12];
    float* out = (float*)d_out;

    const int n = in_sizes[0];
    const int e = in_sizes[3] / 2;

    const int SMEM_G1 = 65536;              // pipeline 40K, epilogue reuse 64K
    const int SMEM_G3 = 3 * 12288;          // 36 KB
    cudaFuncSetAttribute((const void*)k_gemm_mma<1, 1, LM, 128, 256>,
                         cudaFuncAttributeMaxDynamicSharedMemorySize, SMEM_G1);
    cudaFuncSetAttribute((const void*)k_gemm_mma<0, 3, HH, 64, 128>,
                         cudaFuncAttributeMaxDynamicSharedMemorySize, SMEM_G3);

    // --- graph preprocessing (detect+init fused) ---
    const int nblk = (n + 1023) / 1024;
    k_prep  <<<(n + 255) / 256, 256>>>((const unsigned int*)ei, n);
    k_count <<<(e + 255) / 256, 256>>>(ei, ew, e);
    k_scanA <<<nblk, 1024>>>(n);
    k_scanB <<<nblk, 1024>>>(n, e);
    k_fill  <<<(e + 255) / 256, 256>>>(ei, ew, e);

    // --- weight transpose+convert + hp1f zero (single fused launch) ---
    {
        const int tot = LM * LM + LM * HH + HH * OUTC + NN * HH;
        k_cvt_w<<<(tot + 255) / 256, 256>>>(Wl, W1, W3);
    }

    // --- fused layer0 + conv1 projection (mma):
    //     h1 tile in smem only; hp1f += h1 @ W1 (split-K atomics) ---
    {
        dim3 grid(LM / 128, (n + 127) / 128);
        k_gemm_mma<1, 1, LM, 128, 256><<<grid, 256, SMEM_G1>>>(
            n, xout, c, x, Wc, Wa, bl);
    }
    // --- hp1 fp32 -> fp16 for gather ---
    {
        long long tot2 = (long long)NN * HH / 2;
        k_cvt_hp1<<<(unsigned)((tot2 + 511) / 512), 512>>>(tot2);
    }
    // --- conv1 aggregation + bias + relu: h2 (fp16) ---
    k_agg_h<<<(n * 32 + 255) / 256, 256>>>(b1, n);

    // --- conv3 projection (mma): hp3 = h2 @ W3 -> fp32 ---
    {
        dim3 grid(1, (n + 127) / 128);
        k_gemm_mma<0, 3, HH, 64, 128><<<grid, 128, SMEM_G3>>>(
            n, nullptr, nullptr, nullptr, nullptr, nullptr, nullptr);
    }
    // --- conv3 aggregation + bias: out (fp32) ---
    k_agg_f<<<(n * 32 + 255) / 256, 256>>>(b3, out, n);
}

// round 17
// speedup vs baseline: 1.0752x; 1.0752x over previous
#include <cuda_runtime.h>
#include <cuda_fp16.h>
#include <cstdint>

// Problem constants (fixed shapes for this problem instance)
#define NN   50000
#define EE   800000
#define LM   1024
#define HH   128
#define OUTC 64

// ---------------- scratch (static __device__, no allocation) ----------------
__device__ __half g_h1h[(size_t)NN * LM];   // h1 fp16
__device__ __half g_wth [(size_t)LM * LM];  // Wl^T fp16  [1024,1024]
__device__ __half g_w1th[(size_t)HH * LM];  // W1^T fp16  [128,1024]
__device__ __half g_w3t [(size_t)OUTC * HH];// W3^T fp16  [64,128]
__device__ __half g_hp1h[(size_t)NN * HH];  // h1 @ W1 (fp16)
__device__ __half g_h2h [(size_t)NN * HH];  // conv1 output relu'd (fp16)
__device__ float  g_hp3[(size_t)NN * OUTC]; // h2 @ W3 (fp32)
__device__ float g_deg [NN];
__device__ float g_dis [NN];
__device__ int   g_cnt [NN];
__device__ int   g_rowptr[NN + 1];
__device__ int   g_bsum[64];
__device__ int   g_csr_src [EE];
__device__ float g_csr_coef[EE];
__device__ int   g_is64;

// ---------------- portable PTX helpers (sm_80+, compile for compute_103) ----
__device__ __forceinline__ uint32_t smem_to_u32(const void* p) {
    uint32_t a;
    asm("{ .reg .u64 t; cvta.to.shared.u64 t, %1; cvt.u32.u64 %0, t; }" : "=r"(a) : "l"(p));
    return a;
}
#define CP_ASYNC16(saddr, gaddr, sz) \
    asm volatile("cp.async.cg.shared.global [%0], [%1], 16, %2;" \
        :: "r"(saddr), "l"(gaddr), "r"(sz))
#define CP_COMMIT() asm volatile("cp.async.commit_group;" ::: "memory")
#define CP_WAIT(n)  asm volatile("cp.async.wait_group %0;" :: "n"(n) : "memory")
#define LDSM_X4(R, ADDR) \
    asm volatile("ldmatrix.sync.aligned.m8n8.x4.shared.b16 {%0,%1,%2,%3}, [%4];" \
        : "=r"((R)[0]), "=r"((R)[1]), "=r"((R)[2]), "=r"((R)[3]) : "r"(ADDR))

__device__ __forceinline__ void mma_fp16(float* d, const uint32_t* a,
                                         uint32_t b0, uint32_t b1) {
    asm volatile(
        "mma.sync.aligned.m16n8k16.row.col.f32.f16.f16.f32 "
        "{%0,%1,%2,%3}, {%4,%5,%6,%7}, {%8,%9}, {%0,%1,%2,%3};"
        : "+f"(d[0]), "+f"(d[1]), "+f"(d[2]), "+f"(d[3])
        : "r"(a[0]), "r"(a[1]), "r"(a[2]), "r"(a[3]), "r"(b0), "r"(b1));
}

// ---------------- buffer selectors (avoid host symbol lookups) ----------------
__device__ __forceinline__ const __half* sel_a(int SEL) {
    if (SEL == 2) return g_h1h;
    return g_h2h;
}
__device__ __forceinline__ const __half* sel_b(int SEL) {
    if (SEL == 1) return g_wth;
    if (SEL == 2) return g_w1th;
    return g_w3t;
}

// edge index fetch honoring detected dtype
__device__ __forceinline__ int edge_at(const void* ei, long long idx) {
    if (g_is64) return (int)((const long long*)ei)[idx];
    return ((const int*)ei)[idx];
}

// ---------------- fused dtype detection + init ----------------
__global__ void k_prep(const unsigned int* __restrict__ w, int n) {
    int i = blockIdx.x * blockDim.x + threadIdx.x;
    if (i == 0) {
        int is64 = 1;
        for (int j = 1; j < 64; j += 2)
            if (w[j] != 0u) { is64 = 0; break; }
        g_is64 = is64;
    }
    if (i < n) { g_deg[i] = 1.0f; g_cnt[i] = 0; }
}

__global__ void k_count(const void* __restrict__ ei, const float* __restrict__ ew, int e_) {
    int e = blockIdx.x * blockDim.x + threadIdx.x;
    if (e >= e_) return;
    int d = edge_at(ei, (long long)e_ + e);
    atomicAdd(&g_deg[d], ew[e]);
    atomicAdd(&g_cnt[d], 1);
}

// multi-block scan, phase A: per-block local exclusive scan + block totals
__global__ void k_scanA(int n) {
    __shared__ int wsum[32];
    int tid  = threadIdx.x;
    int warp = tid >> 5;
    int idx  = blockIdx.x * 1024 + tid;
    int v = (idx < n) ? g_cnt[idx] : 0;
    int inc = v;
    #pragma unroll
    for (int o = 1; o < 32; o <<= 1) {
        int nb = __shfl_up_sync(0xffffffffu, inc, o);
        if ((tid & 31) >= o) inc += nb;
    }
    if ((tid & 31) == 31) wsum[warp] = inc;
    __syncthreads();
    if (tid < 32) {
        int w = wsum[tid];
        #pragma unroll
        for (int o = 1; o < 32; o <<= 1) {
            int nb = __shfl_up_sync(0xffffffffu, w, o);
            if (tid >= o) w += nb;
        }
        wsum[tid] = w;
    }
    __syncthreads();
    int excl = inc - v + ((warp > 0) ? wsum[warp - 1] : 0);
    if (idx < n) {
        g_rowptr[idx] = excl;
        g_cnt[idx]    = 0;
        g_dis[idx]    = rsqrtf(g_deg[idx]);
    }
    if (tid == 0) g_bsum[blockIdx.x] = wsum[31];
}

// phase B: add block offsets
__global__ void k_scanB(int n, int e_) {
    __shared__ int s_off;
    int tid = threadIdx.x;
    if (tid < 32) {
        int acc = 0;
        for (int i = tid; i < (int)blockIdx.x; i += 32) acc += g_bsum[i];
        #pragma unroll
        for (int o = 16; o > 0; o >>= 1)
            acc += __shfl_down_sync(0xffffffffu, acc, o);
        if (tid == 0) s_off = acc;
    }
    __syncthreads();
    int idx = blockIdx.x * 1024 + tid;
    if (idx < n) g_rowptr[idx] += s_off;
    if (idx == n - 1) g_rowptr[n] = e_;
}

__global__ void k_fill(const void* __restrict__ ei, const float* __restrict__ ew, int e_) {
    int e = blockIdx.x * blockDim.x + threadIdx.x;
    if (e >= e_) return;
    int s = edge_at(ei, e);
    int d = edge_at(ei, (long long)e_ + e);
    int p = g_rowptr[d] + atomicAdd(&g_cnt[d], 1);
    g_csr_src[p]  = s;
    g_csr_coef[p] = g_dis[s] * ew[e] * g_dis[d];
}

// ---------------- fused weight transpose+convert (all three W) -------------
__global__ void k_cvt_w(const float* __restrict__ Wl, const float* __restrict__ W1,
                        const float* __restrict__ W3) {
    int idx = blockIdx.x * blockDim.x + threadIdx.x;
    if (idx < LM * LM) {
        int k = idx / LM, nn = idx % LM;
        g_wth[(size_t)nn * LM + k] = __float2half(Wl[idx]);
        return;
    }
    idx -= LM * LM;
    if (idx < LM * HH) {
        int k = idx / HH, nn = idx % HH;
        g_w1th[(size_t)nn * LM + k] = __float2half(W1[idx]);
        return;
    }
    idx -= LM * HH;
    if (idx < HH * OUTC) {
        int k = idx / OUTC, nn = idx % OUTC;
        g_w3t[(size_t)nn * HH + k] = __float2half(W3[idx]);
    }
}

// ---------------- mma.sync fp16 GEMM (generalized, R14 structure) ----------
// AF32=1: A fp32 in gmem (LDG->cvt->STS, 2-stage A); B via 3-stage cp.async.
// AF32=0: A+B via 3-stage cp.async (strided loops, any THREADS).
// EPI=1: layer0 epilogue (bias+rank1+relu) -> g_h1h fp16 (stride LM)
// EPI=2: fp16 -> g_hp1h (stride HH)
// EPI=3: fp32 -> g_hp3  (stride OUTC)
template <int EPI, int AF32, int ASEL, int BSEL, int KDIM, int BN, int THREADS>
__global__ __launch_bounds__(THREADS)
void k_gemm_mma(int M, const float* __restrict__ Af32,
                const float* __restrict__ cvec, const float* __restrict__ xvec,
                const float* __restrict__ Wc,   const float* __restrict__ Wa,
                const float* __restrict__ bl) {
    constexpr int BK  = 32;
    constexpr int NIT = KDIM / BK;
    constexpr int ASZ = 8192;
    constexpr int BSZ = BN * BK * 2;
    constexpr int NSTAGE = 3;

    extern __shared__ char smem[];
    const uint32_t sbase0 = smem_to_u32(smem);
    const uint32_t bbase = AF32 ? (sbase0 + 2 * ASZ) : sbase0;
    constexpr int BSTRIDE = AF32 ? BSZ : (ASZ + BSZ);
    constexpr uint32_t BOFF = AF32 ? 0 : ASZ;

    const int tid    = threadIdx.x;
    const int lane   = tid & 31;
    const int wid    = tid >> 5;
    const int warp_m = wid & 3;
    const int warp_n = wid >> 2;

    const int block_row = blockIdx.y * 128;
    const int block_col = blockIdx.x * BN;

    const __half* __restrict__ Ah = sel_a(ASEL);
    const __half* __restrict__ Bh = sel_b(BSEL);

    const int r0  = tid >> 2,          cb0 = tid & 3;
    const int r1  = (tid + 256) >> 2,  cb1 = tid & 3;
    const uint32_t so0 = (uint32_t)(r0 * 64 + ((cb0 ^ ((r0 >> 1) & 3)) * 16));
    const uint32_t so1 = (uint32_t)(r1 * 64 + ((cb1 ^ ((r1 >> 1) & 3)) * 16));

    auto issue_B = [&](int stage, int k0) {
        uint32_t sb = bbase + stage * BSTRIDE + BOFF;
        #pragma unroll
        for (int i = tid; i < BN * 4; i += THREADS) {
            int r = i >> 2, cb = i & 3;
            uint32_t so = (uint32_t)(r * 64 + ((cb ^ ((r >> 1) & 3)) * 16));
            size_t gb = (size_t)(block_col + r) * KDIM + k0 + cb * 8;
            CP_ASYNC16(sb + so, (const char*)(Bh + gb), 16u);
        }
        CP_COMMIT();
    };
    auto issue_A_async = [&](int stage, int k0) {   // AF32==0, any THREADS
        uint32_t sb = bbase + stage * BSTRIDE;
        #pragma unroll
        for (int i = tid; i < 512; i += THREADS) {
            int r = i >> 2, cb = i & 3;
            uint32_t so = (uint32_t)(r * 64 + ((cb ^ ((r >> 1) & 3)) * 16));
            long long arow = block_row + r;
            size_t ga = (size_t)arow * KDIM + k0 + cb * 8;
            uint32_t asz = (arow < M) ? 16u : 0u;
            CP_ASYNC16(sb + so, (const char*)(Ah + ga), asz);
        }
    };

    float4 arg[4];
    auto ldg_A = [&](int k0) {
        long long arow0 = block_row + r0;
        long long arow1 = block_row + r1;
        if (arow0 < M) {
            const float* p = Af32 + (size_t)arow0 * KDIM + k0 + cb0 * 8;
            arg[0] = *(const float4*)p;
            arg[1] = *(const float4*)(p + 4);
        } else {
            arg[0] = arg[1] = make_float4(0.f, 0.f, 0.f, 0.f);
        }
        if (arow1 < M) {
            const float* p = Af32 + (size_t)arow1 * KDIM + k0 + cb1 * 8;
            arg[2] = *(const float4*)p;
            arg[3] = *(const float4*)(p + 4);
        } else {
            arg[2] = arg[3] = make_float4(0.f, 0.f, 0.f, 0.f);
        }
    };
    auto sts_A = [&](int buf) {
        uint32_t off = buf * ASZ;
        uint4 v;
        __half2 h;
        h = __floats2half2_rn(arg[0].x, arg[0].y); v.x = *(uint32_t*)&h;
        h = __floats2half2_rn(arg[0].z, arg[0].w); v.y = *(uint32_t*)&h;
        h = __floats2half2_rn(arg[1].x, arg[1].y); v.z = *(uint32_t*)&h;
        h = __floats2half2_rn(arg[1].z, arg[1].w); v.w = *(uint32_t*)&h;
        *(uint4*)(smem + off + so0) = v;
        h = __floats2half2_rn(arg[2].x, arg[2].y); v.x = *(uint32_t*)&h;
        h = __floats2half2_rn(arg[2].z, arg[2].w); v.y = *(uint32_t*)&h;
        h = __floats2half2_rn(arg[3].x, arg[3].y); v.z = *(uint32_t*)&h;
        h = __floats2half2_rn(arg[3].z, arg[3].w); v.w = *(uint32_t*)&h;
        *(uint4*)(smem + off + so1) = v;
    };

    float acc[2][8][4];
    #pragma unroll
    for (int i = 0; i < 2; i++)
        #pragma unroll
        for (int j = 0; j < 8; j++)
            #pragma unroll
            for (int q = 0; q < 4; q++) acc[i][j][q] = 0.0f;

    if (AF32) {
        ldg_A(0);
        issue_B(0, 0);
        issue_B(1, BK);
        sts_A(0);
        CP_WAIT(1);
        __syncthreads();
    } else {
        issue_A_async(0, 0); issue_B(0, 0);
        issue_A_async(1, BK); issue_B(1, BK);
    }

    int stage = 0;
    for (int it = 0; it < NIT; it++) {
        if (AF32) {
            if (it + 1 < NIT) ldg_A((it + 1) * BK);
            if (it + 2 < NIT) issue_B((it + 2) % NSTAGE, (it + 2) * BK);
        } else {
            if (it + 2 < NIT) {
                issue_A_async((it + 2) % NSTAGE, (it + 2) * BK);
                issue_B((it + 2) % NSTAGE, (it + 2) * BK);
                CP_WAIT(2);
            } else {
                CP_WAIT(0);
            }
            __syncthreads();
        }

        const uint32_t abuf = AF32 ? (sbase0 + (it & 1) * ASZ)
                                   : (bbase + stage * BSTRIDE);
        const uint32_t bbuf = bbase + stage * BSTRIDE + BOFF;
        #pragma unroll
        for (int ks = 0; ks < 2; ks++) {
            uint32_t aH[2][4];
            #pragma unroll
            for (int mt = 0; mt < 2; mt++) {
                int row = warp_m * 32 + mt * 16 + (lane & 15);
                int cb  = ks * 2 + (lane >> 4);
                uint32_t off = (uint32_t)(row * 64 + ((cb ^ ((row >> 1) & 3)) * 16));
                LDSM_X4(aH[mt], abuf + off);
            }
            #pragma unroll
            for (int g = 0; g < 4; g++) {
                uint32_t bh[4];
                int row = warp_n * 64 + g * 16 + (lane & 15);
                int cb  = ks * 2 + (lane >> 4);
                uint32_t off = (uint32_t)(row * 64 + ((cb ^ ((row >> 1) & 3)) * 16));
                LDSM_X4(bh, bbuf + off);
                #pragma unroll
                for (int mt = 0; mt < 2; mt++) {
                    #pragma unroll
                    for (int sub = 0; sub < 2; sub++) {
                        int nt = g * 2 + sub;
                        mma_fp16(acc[mt][nt], aH[mt], bh[sub], bh[sub + 2]);
                    }
                }
            }
        }
        __syncthreads();
        if (AF32) {
            if (it + 1 < NIT) sts_A((it + 1) & 1);
            if (it + 2 < NIT) { CP_WAIT(1); }
            else if (it + 1 < NIT) { CP_WAIT(0); }
            __syncthreads();
        }
        stage = (stage + 1 == NSTAGE) ? 0 : stage + 1;
    }

    // ---------------- epilogue ----------------
    #pragma unroll
    for (int nt = 0; nt < 8; nt++) {
        int col = block_col + warp_n * 64 + nt * 8 + (lane & 3) * 2;
        float bl0 = 0.f, bl1 = 0.f, wc0 = 0.f, wc1 = 0.f, wa0 = 0.f, wa1 = 0.f;
        if (EPI == 1) {
            bl0 = bl[col];  bl1 = bl[col + 1];
            wc0 = Wc[col];  wc1 = Wc[col + 1];
            wa0 = Wa[col];  wa1 = Wa[col + 1];
        }
        #pragma unroll
        for (int mt = 0; mt < 2; mt++) {
            int rbase = block_row + warp_m * 32 + mt * 16 + (lane >> 2);
            #pragma unroll
            for (int h = 0; h < 2; h++) {
                int row = rbase + h * 8;
                if (row >= M) continue;
                float v0 = acc[mt][nt][h * 2 + 0];
                float v1 = acc[mt][nt][h * 2 + 1];
                if (EPI == 1) {
                    float cv = cvec[row], xv = xvec[row];
                    v0 = fmaxf(v0 + bl0 + cv * wc0 + xv * wa0, 0.f);
                    v1 = fmaxf(v1 + bl1 + cv * wc1 + xv * wa1, 0.f);
                    __half2 hh;
                    hh.x = __float2half(v0);
                    hh.y = __float2half(v1);
                    *(__half2*)&g_h1h[(size_t)row * LM + col] = hh;
                } else if (EPI == 2) {
                    __half2 hh;
                    hh.x = __float2half(v0);
                    hh.y = __float2half(v1);
                    *(__half2*)&g_hp1h[(size_t)row * HH + col] = hh;
                } else {
                    float2 f2; f2.x = v0; f2.y = v1;
                    *(float2*)&g_hp3[(size_t)row * OUTC + col] = f2;
                }
            }
        }
    }
}

// ---------------- conv1 aggregation (fp16 in/out, CSR gather, warp/node) ----
__global__ void k_agg_h(const float* __restrict__ bias, int n) {
    int warp = (blockIdx.x * blockDim.x + threadIdx.x) >> 5;
    int lane = threadIdx.x & 31;
    if (warp >= n) return;
    const int node = warp;
    float acc[4];

    float selfc = g_dis[node] * g_dis[node];
    {
        uint2 v = *(const uint2*)&g_hp1h[(size_t)node * HH + lane * 4];
        float2 fa = __half22float2(*reinterpret_cast<__half2*>(&v.x));
        float2 fb = __half22float2(*reinterpret_cast<__half2*>(&v.y));
        acc[0] = selfc * fa.x; acc[1] = selfc * fa.y;
        acc[2] = selfc * fb.x; acc[3] = selfc * fb.y;
    }
    int beg = g_rowptr[node];
    int end = g_rowptr[node + 1];
    for (int e = beg; e < end; e++) {
        int   s  = g_csr_src[e];
        float cf = g_csr_coef[e];
        uint2 v = *(const uint2*)&g_hp1h[(size_t)s * HH + lane * 4];
        float2 fa = __half22float2(*reinterpret_cast<__half2*>(&v.x));
        float2 fb = __half22float2(*reinterpret_cast<__half2*>(&v.y));
        acc[0] = fmaf(cf, fa.x, acc[0]);
        acc[1] = fmaf(cf, fa.y, acc[1]);
        acc[2] = fmaf(cf, fb.x, acc[2]);
        acc[3] = fmaf(cf, fb.y, acc[3]);
    }
    float b0 = bias[lane * 4 + 0], b1 = bias[lane * 4 + 1];
    float b2 = bias[lane * 4 + 2], b3 = bias[lane * 4 + 3];
    __half2 o0, o1;
    o0.x = __float2half(fmaxf(acc[0] + b0, 0.f));
    o0.y = __float2half(fmaxf(acc[1] + b1, 0.f));
    o1.x = __float2half(fmaxf(acc[2] + b2, 0.f));
    o1.y = __float2half(fmaxf(acc[3] + b3, 0.f));
    uint2 ov;
    ov.x = *reinterpret_cast<uint32_t*>(&o0);
    ov.y = *reinterpret_cast<uint32_t*>(&o1);
    *(uint2*)&g_h2h[(size_t)node * HH + lane * 4] = ov;
}

// ---------------- conv3 aggregation (fp32, writes final out) ----------------
__global__ void k_agg_f(const float* __restrict__ bias, float* __restrict__ out, int n) {
    int warp = (blockIdx.x * blockDim.x + threadIdx.x) >> 5;
    int lane = threadIdx.x & 31;
    if (warp >= n) return;
    const int node = warp;
    float acc[2];

    float selfc = g_dis[node] * g_dis[node];
    {
        float2 v = *(const float2*)&g_hp3[(size_t)node * OUTC + lane * 2];
        acc[0] = selfc * v.x; acc[1] = selfc * v.y;
    }
    int beg = g_rowptr[node];
    int end = g_rowptr[node + 1];
    for (int e = beg; e < end; e++) {
        int   s  = g_csr_src[e];
        float cf = g_csr_coef[e];
        float2 v = *(const float2*)&g_hp3[(size_t)s * OUTC + lane * 2];
        acc[0] = fmaf(cf, v.x, acc[0]);
        acc[1] = fmaf(cf, v.y, acc[1]);
    }
    float2 o;
    o.x = acc[0] + bias[lane * 2 + 0];
    o.y = acc[1] + bias[lane * 2 + 1];
    *(float2*)&out[(size_t)node * OUTC + lane * 2] = o;
}

// ---------------- launch ----------------
extern "C" void kernel_launch(void* const* d_in, const int* in_sizes, int n_in,
                              void* d_out, int out_size) {
    const float* x    = (const float*)d_in[0];
    const float* xout = (const float*)d_in[1];
    const float* c    = (const float*)d_in[2];
    const void*  ei   = d_in[3];
    const float* ew   = (const float*)d_in[4];
    const float* Wa   = (const float*)d_in[5];
    const float* Wc   = (const float*)d_in[6];
    const float* Wl   = (const float*)d_in[7];
    const float* bl   = (const float*)d_in[8];
    const float* W1   = (const float*)d_in[9];
    const float* b1   = (const float*)d_in[10];
    const float* W3   = (const float*)d_in[11];
    const float* b3   = (const float*)d_in[12];
    float* out = (float*)d_out;

    const int n = in_sizes[0];
    const int e = in_sizes[3] / 2;

    const int SMEM_G1  = 2 * 8192 + 3 * 8192;   // 40 KB (A 2-stage + B 3-stage)
    const int SMEM_G2  = 3 * 16384;             // 48 KB
    const int SMEM_G3  = 3 * 12288;             // 36 KB
    cudaFuncSetAttribute((const void*)k_gemm_mma<1, 1, 0, 1, LM, 128, 256>,
                         cudaFuncAttributeMaxDynamicSharedMemorySize, SMEM_G1);
    cudaFuncSetAttribute((const void*)k_gemm_mma<2, 0, 2, 2, LM, 128, 256>,
                         cudaFuncAttributeMaxDynamicSharedMemorySize, SMEM_G2);
    cudaFuncSetAttribute((const void*)k_gemm_mma<3, 0, 3, 3, HH, 64, 128>,
                         cudaFuncAttributeMaxDynamicSharedMemorySize, SMEM_G3);

    // One-time stream/event creation (first call = correctness run, not
    // captured; capture call reuses the same handles, enqueues identical work).
    static cudaStream_t s2 = nullptr;
    static cudaEvent_t evFork = nullptr, evJoin = nullptr;
    if (s2 == nullptr) {
        cudaStreamCreateWithFlags(&s2, cudaStreamNonBlocking);
        cudaEventCreateWithFlags(&evFork, cudaEventDisableTiming);
        cudaEventCreateWithFlags(&evJoin, cudaEventDisableTiming);
    }

    // ---- fork: graph preprocessing runs on s2, concurrent with GEMM chain ----
    cudaEventRecord(evFork, 0);
    cudaStreamWaitEvent(s2, evFork, 0);

    const int nblk = (n + 1023) / 1024;
    k_prep  <<<(n + 255) / 256, 256, 0, s2>>>((const unsigned int*)ei, n);
    k_count <<<(e + 255) / 256, 256, 0, s2>>>(ei, ew, e);
    k_scanA <<<nblk, 1024, 0, s2>>>(n);
    k_scanB <<<nblk, 1024, 0, s2>>>(n, e);
    k_fill  <<<(e + 255) / 256, 256, 0, s2>>>(ei, ew, e);
    cudaEventRecord(evJoin, s2);

    // ---- main stream: weights + GEMM1 + GEMM2 (independent of graph) ----
    {
        const int tot = LM * LM + LM * HH + HH * OUTC;
        k_cvt_w<<<(tot + 255) / 256, 256>>>(Wl, W1, W3);
    }
    // layer 0 (mma, fused fp32->fp16 A-load): h1 = relu(xout@Wl + epi) -> fp16
    {
        dim3 grid(LM / 128, (n + 127) / 128);
        k_gemm_mma<1, 1, 0, 1, LM, 128, 256><<<grid, 256, SMEM_G1>>>(
            n, xout, c, x, Wc, Wa, bl);
    }
    // conv1 projection (mma): hp1 = h1 @ W1 -> fp16
    {
        dim3 grid(HH / 128, (n + 127) / 128);
        k_gemm_mma<2, 0, 2, 2, LM, 128, 256><<<grid, 256, SMEM_G2>>>(
            n, nullptr, nullptr, nullptr, nullptr, nullptr, nullptr);
    }

    // ---- join: aggregation needs the CSR ----
    cudaStreamWaitEvent(0, evJoin, 0);

    // conv1 aggregation + bias + relu: h2 (fp16)
    k_agg_h<<<(n * 32 + 255) / 256, 256>>>(b1, n);
    // conv3 projection (mma): hp3 = h2 @ W3 -> fp32
    {
        dim3 grid(1, (n + 127) / 128);
        k_gemm_mma<3, 0, 3, 3, HH, 64, 128><<<grid, 128, SMEM_G3>>>(
            n, nullptr, nullptr, nullptr, nullptr, nullptr, nullptr);
    }
    // conv3 aggregation + bias: out (fp32)
    k_agg_f<<<(n * 32 + 255) / 256, 256>>>(b3, out, n);
}